// round 1
// baseline (speedup 1.0000x reference)
#include <cuda_runtime.h>
#include <math.h>

#define D_DIM 512
#define NB 4096     // queries
#define NK 16384    // support keys
#define BETA 5.5f
#define ALPHA 0.5f

// Scratch (static __device__ arrays are the allowed scratch mechanism)
__device__ float g_ck[(size_t)NK * D_DIM];              // normalized keys   (32 MB)
__device__ float g_qn[(size_t)NB * D_DIM];              // normalized query  (8 MB)
__device__ float g_aff[(size_t)NB * NK];                // affinity          (256 MB)

// ---------------------------------------------------------------------------
// Row L2-normalization: one warp per row of 512 floats.
// dst_sel: 0 -> g_qn, 1 -> g_ck
// ---------------------------------------------------------------------------
__global__ void __launch_bounds__(256) norm_rows(const float* __restrict__ src,
                                                 int rows, int dst_sel) {
    int w = (blockIdx.x * blockDim.x + threadIdx.x) >> 5;
    if (w >= rows) return;
    int lane = threadIdx.x & 31;

    float* dst = dst_sel ? g_ck : g_qn;

    const float4* s = (const float4*)(src + (size_t)w * D_DIM);
    float4* d = (float4*)(dst + (size_t)w * D_DIM);

    float4 v[4];
    float ss = 0.f;
#pragma unroll
    for (int i = 0; i < 4; i++) {
        v[i] = s[lane + 32 * i];
        ss += v[i].x * v[i].x + v[i].y * v[i].y + v[i].z * v[i].z + v[i].w * v[i].w;
    }
#pragma unroll
    for (int o = 16; o; o >>= 1) ss += __shfl_xor_sync(0xffffffffu, ss, o);

    float inv = 1.0f / fmaxf(sqrtf(ss), 1e-12f);
#pragma unroll
    for (int i = 0; i < 4; i++) {
        v[i].x *= inv; v[i].y *= inv; v[i].z *= inv; v[i].w *= inv;
        d[lane + 32 * i] = v[i];
    }
}

// ---------------------------------------------------------------------------
// GEMM1: Aff[b][n] = exp(BETA * dot(qn[b], ck[n]) - BETA)
// Both operands are K-major (D contiguous) -> NT-style GEMM.
// Tile 64x64, BK=16, 256 threads, 4x4 microtile.
// ---------------------------------------------------------------------------
__global__ void __launch_bounds__(256) gemm1_kernel() {
    __shared__ float As[16][64];   // [k][m]
    __shared__ float Bs[16][64];   // [k][n]

    const int m0 = blockIdx.y * 64;
    const int n0 = blockIdx.x * 64;
    const int tid = threadIdx.x;

    const int lr = tid >> 2;          // 0..63 row being loaded
    const int lc = (tid & 3) << 2;    // k offset 0,4,8,12

    const int tx = tid & 15;          // n-group
    const int ty = tid >> 4;          // m-group

    const float* Aptr = g_qn + (size_t)(m0 + lr) * D_DIM + lc;
    const float* Bptr = g_ck + (size_t)(n0 + lr) * D_DIM + lc;

    float acc[4][4] = {};

    for (int kt = 0; kt < D_DIM; kt += 16) {
        float4 av = *(const float4*)(Aptr + kt);
        float4 bv = *(const float4*)(Bptr + kt);
        As[lc + 0][lr] = av.x; As[lc + 1][lr] = av.y;
        As[lc + 2][lr] = av.z; As[lc + 3][lr] = av.w;
        Bs[lc + 0][lr] = bv.x; Bs[lc + 1][lr] = bv.y;
        Bs[lc + 2][lr] = bv.z; Bs[lc + 3][lr] = bv.w;
        __syncthreads();

#pragma unroll
        for (int k = 0; k < 16; k++) {
            float a[4], b[4];
            *(float4*)a = *(const float4*)&As[k][ty << 2];
            *(float4*)b = *(const float4*)&Bs[k][tx << 2];
#pragma unroll
            for (int i = 0; i < 4; i++)
#pragma unroll
                for (int j = 0; j < 4; j++)
                    acc[i][j] = fmaf(a[i], b[j], acc[i][j]);
        }
        __syncthreads();
    }

#pragma unroll
    for (int i = 0; i < 4; i++) {
        int row = m0 + (ty << 2) + i;
        float4 v;
        v.x = __expf(fmaf(BETA, acc[i][0], -BETA));
        v.y = __expf(fmaf(BETA, acc[i][1], -BETA));
        v.z = __expf(fmaf(BETA, acc[i][2], -BETA));
        v.w = __expf(fmaf(BETA, acc[i][3], -BETA));
        *(float4*)&g_aff[(size_t)row * NK + n0 + (tx << 2)] = v;
    }
}

// ---------------------------------------------------------------------------
// GEMM2: Out[b][d] = Qorig[b][d] + ALPHA * sum_n Aff[b][n] * ck[n][d]
// A row-major [M=4096][K=16384] (k contiguous), B = ck [K=16384][N=512] (n contiguous).
// Tile 64x64, BK=16, 256 threads, 4x4 microtile.
// ---------------------------------------------------------------------------
__global__ void __launch_bounds__(256) gemm2_kernel(const float* __restrict__ Qorig,
                                                    float* __restrict__ Out) {
    __shared__ float As[16][64];   // [k][m]  (transposed on store)
    __shared__ float Bs[16][64];   // [k][n]  (direct)

    const int m0 = blockIdx.y * 64;   // b
    const int n0 = blockIdx.x * 64;   // d
    const int tid = threadIdx.x;

    const int ar = tid >> 2;          // m row 0..63
    const int ac = (tid & 3) << 2;    // k offset 0,4,8,12
    const int br = tid >> 4;          // k row 0..15
    const int bc = (tid & 15) << 2;   // n offset

    const int tx = tid & 15;
    const int ty = tid >> 4;

    float acc[4][4] = {};

    for (int kt = 0; kt < NK; kt += 16) {
        float4 av = *(const float4*)(g_aff + (size_t)(m0 + ar) * NK + kt + ac);
        float4 bv = *(const float4*)(g_ck + (size_t)(kt + br) * D_DIM + n0 + bc);
        As[ac + 0][ar] = av.x; As[ac + 1][ar] = av.y;
        As[ac + 2][ar] = av.z; As[ac + 3][ar] = av.w;
        *(float4*)&Bs[br][bc] = bv;
        __syncthreads();

#pragma unroll
        for (int k = 0; k < 16; k++) {
            float a[4], b[4];
            *(float4*)a = *(const float4*)&As[k][ty << 2];
            *(float4*)b = *(const float4*)&Bs[k][tx << 2];
#pragma unroll
            for (int i = 0; i < 4; i++)
#pragma unroll
                for (int j = 0; j < 4; j++)
                    acc[i][j] = fmaf(a[i], b[j], acc[i][j]);
        }
        __syncthreads();
    }

#pragma unroll
    for (int i = 0; i < 4; i++) {
        int row = m0 + (ty << 2) + i;
        float4 qv = *(const float4*)(Qorig + (size_t)row * D_DIM + n0 + (tx << 2));
        float4 o;
        o.x = fmaf(ALPHA, acc[i][0], qv.x);
        o.y = fmaf(ALPHA, acc[i][1], qv.y);
        o.z = fmaf(ALPHA, acc[i][2], qv.z);
        o.w = fmaf(ALPHA, acc[i][3], qv.w);
        *(float4*)&Out[(size_t)row * D_DIM + n0 + (tx << 2)] = o;
    }
}

// ---------------------------------------------------------------------------
extern "C" void kernel_launch(void* const* d_in, const int* in_sizes, int n_in,
                              void* d_out, int out_size) {
    const float* qf;
    const float* sk;
    if (in_sizes[0] == NB * D_DIM) {
        qf = (const float*)d_in[0];
        sk = (const float*)d_in[1];
    } else {
        qf = (const float*)d_in[1];
        sk = (const float*)d_in[0];
    }

    // 8 warps/block -> 8 rows per block
    norm_rows<<<NK / 8, 256>>>(sk, NK, 1);
    norm_rows<<<NB / 8, 256>>>(qf, NB, 0);

    dim3 g1(NK / 64, NB / 64);   // (256, 64)
    gemm1_kernel<<<g1, 256>>>();

    dim3 g2(D_DIM / 64, NB / 64); // (8, 64)
    gemm2_kernel<<<g2, 256>>>(qf, (float*)d_out);
}

// round 4
// speedup vs baseline: 7.7699x; 7.7699x over previous
#include <cuda_runtime.h>
#include <cuda_bf16.h>
#include <stdint.h>
#include <cstdint>
#include <math.h>

typedef unsigned int u32;

#define D_DIM 512
#define NB 4096
#define NK 16384
#define BETA 5.5f
#define ALPHA 0.5f

// bf16 scratch
__device__ __nv_bfloat16 g_qh[(size_t)NB * D_DIM];    // normalized queries (4 MB)
__device__ __nv_bfloat16 g_ckh[(size_t)NK * D_DIM];   // normalized keys    (16 MB)
__device__ __nv_bfloat16 g_aff[(size_t)NB * NK];      // affinity           (128 MB)

// ---------------------------------------------------------------------------
// PTX helpers
// ---------------------------------------------------------------------------
__device__ __forceinline__ void cp16(u32 saddr, const void* g) {
    asm volatile("cp.async.cg.shared.global [%0], [%1], 16;\n" :: "r"(saddr), "l"(g));
}
__device__ __forceinline__ void cp_commit() { asm volatile("cp.async.commit_group;\n"); }
__device__ __forceinline__ void cp_wait1() { asm volatile("cp.async.wait_group 1;\n"); }
__device__ __forceinline__ void cp_wait0() { asm volatile("cp.async.wait_group 0;\n"); }

__device__ __forceinline__ void ldsm_x4(u32* r, u32 addr) {
    asm volatile("ldmatrix.sync.aligned.m8n8.x4.shared.b16 {%0,%1,%2,%3}, [%4];\n"
        : "=r"(r[0]), "=r"(r[1]), "=r"(r[2]), "=r"(r[3]) : "r"(addr));
}
__device__ __forceinline__ void ldsm_x4_t(u32* r, u32 addr) {
    asm volatile("ldmatrix.sync.aligned.m8n8.x4.trans.shared.b16 {%0,%1,%2,%3}, [%4];\n"
        : "=r"(r[0]), "=r"(r[1]), "=r"(r[2]), "=r"(r[3]) : "r"(addr));
}
__device__ __forceinline__ void mma16816(float* c, const u32* a, u32 b0, u32 b1) {
    asm volatile(
        "mma.sync.aligned.m16n8k16.row.col.f32.bf16.bf16.f32 "
        "{%0,%1,%2,%3}, {%4,%5,%6,%7}, {%8,%9}, {%0,%1,%2,%3};\n"
        : "+f"(c[0]), "+f"(c[1]), "+f"(c[2]), "+f"(c[3])
        : "r"(a[0]), "r"(a[1]), "r"(a[2]), "r"(a[3]), "r"(b0), "r"(b1));
}

// ---------------------------------------------------------------------------
// Row L2-normalization -> bf16. One warp per 512-float row.
// ---------------------------------------------------------------------------
__global__ void __launch_bounds__(256) norm_rows(const float* __restrict__ src,
                                                 int rows, int dst_sel) {
    int w = (blockIdx.x * blockDim.x + threadIdx.x) >> 5;
    if (w >= rows) return;
    int lane = threadIdx.x & 31;
    __nv_bfloat16* dst = dst_sel ? g_ckh : g_qh;

    const float4* s = (const float4*)(src + (size_t)w * D_DIM);
    float4 v[4];
    float ss = 0.f;
#pragma unroll
    for (int i = 0; i < 4; i++) {
        v[i] = s[lane + 32 * i];
        ss += v[i].x * v[i].x + v[i].y * v[i].y + v[i].z * v[i].z + v[i].w * v[i].w;
    }
#pragma unroll
    for (int o = 16; o; o >>= 1) {
        ss += __shfl_xor_sync(0xffffffffu, ss, o);
    }
    float inv = 1.0f / fmaxf(sqrtf(ss), 1e-12f);

    uint2* d = (uint2*)(dst + (size_t)w * D_DIM);
#pragma unroll
    for (int i = 0; i < 4; i++) {
        __nv_bfloat162 lo = __floats2bfloat162_rn(v[i].x * inv, v[i].y * inv);
        __nv_bfloat162 hi = __floats2bfloat162_rn(v[i].z * inv, v[i].w * inv);
        uint2 u;
        u.x = *(u32*)&lo;
        u.y = *(u32*)&hi;
        d[lane + 32 * i] = u;
    }
}

// ---------------------------------------------------------------------------
// GEMM1: Aff[b][n] = bf16( exp(BETA * dot(qh[b], ckh[n]) - BETA) )
// Tiles: 128x128x32, 8 warps, warp tile 64x32. A,B both k-contiguous (NT).
// smem rows padded to 80B so each ldmatrix 8-lane phase is conflict-free.
// ---------------------------------------------------------------------------
#define G1_ASZ (128 * 80)   // 10240 bytes per stage (A or B)

__device__ __forceinline__ void g1_load(u32 smb, int s, int m0, int n0,
                                        int kt, int tid) {
    u32 Ab = smb + s * (2 * G1_ASZ);
    u32 Bb = Ab + G1_ASZ;
#pragma unroll
    for (int p = 0; p < 2; p++) {
        int chunk = tid + p * 256;          // 0..511
        int row = chunk >> 2;
        int c = chunk & 3;
        const char* ga = (const char*)g_qh + ((size_t)(m0 + row) * D_DIM + kt * 32 + c * 8) * 2;
        cp16(Ab + row * 80 + c * 16, ga);
        const char* gb = (const char*)g_ckh + ((size_t)(n0 + row) * D_DIM + kt * 32 + c * 8) * 2;
        cp16(Bb + row * 80 + c * 16, gb);
    }
    cp_commit();
}

__global__ void __launch_bounds__(256) gemm1_kernel() {
    __shared__ __align__(16) char sm[2 * 2 * G1_ASZ];  // 40 KB
    const int tid = threadIdx.x;
    const int warp = tid >> 5;
    const int lane = tid & 31;
    const int m0 = blockIdx.y * 128;
    const int n0 = blockIdx.x * 128;
    const int wm = (warp >> 2) * 64;
    const int wn = (warp & 3) * 32;
    const u32 smb = (u32)__cvta_generic_to_shared(sm);

    float acc[4][4][4] = {};

    g1_load(smb, 0, m0, n0, 0, tid);

    const int NT = D_DIM / 32;  // 16
    for (int kt = 0; kt < NT; kt++) {
        if (kt + 1 < NT) {
            g1_load(smb, (kt + 1) & 1, m0, n0, kt + 1, tid);
            cp_wait1();
        } else {
            cp_wait0();
        }
        __syncthreads();

        u32 Ab = smb + (kt & 1) * (2 * G1_ASZ);
        u32 Bb = Ab + G1_ASZ;
#pragma unroll
        for (int ks = 0; ks < 2; ks++) {
            u32 a[4][4];
            u32 b[2][4];
#pragma unroll
            for (int mi = 0; mi < 4; mi++) {
                ldsm_x4(a[mi], Ab + (wm + mi * 16 + (lane & 15)) * 80 + ks * 32 + (lane >> 4) * 16);
            }
#pragma unroll
            for (int j = 0; j < 2; j++) {
                ldsm_x4(b[j], Bb + (wn + j * 16 + (lane & 15)) * 80 + ks * 32 + (lane >> 4) * 16);
            }
#pragma unroll
            for (int mi = 0; mi < 4; mi++) {
#pragma unroll
                for (int j = 0; j < 2; j++) {
                    mma16816(acc[mi][j * 2 + 0], a[mi], b[j][0], b[j][2]);  // n rows 0-7
                    mma16816(acc[mi][j * 2 + 1], a[mi], b[j][1], b[j][3]);  // n rows 8-15
                }
            }
        }
        __syncthreads();
    }

    // Epilogue: exp + bf16 store
#pragma unroll
    for (int mi = 0; mi < 4; mi++) {
#pragma unroll
        for (int ni = 0; ni < 4; ni++) {
            int col = n0 + wn + ni * 8 + (lane & 3) * 2;
#pragma unroll
            for (int h = 0; h < 2; h++) {
                int row = m0 + wm + mi * 16 + (lane >> 2) + h * 8;
                float e0 = __expf(fmaf(BETA, acc[mi][ni][2 * h + 0], -BETA));
                float e1 = __expf(fmaf(BETA, acc[mi][ni][2 * h + 1], -BETA));
                __nv_bfloat162 v = __floats2bfloat162_rn(e0, e1);
                *(u32*)(&g_aff[(size_t)row * NK + col]) = *(u32*)&v;
            }
        }
    }
}

// ---------------------------------------------------------------------------
// GEMM2: Out[b][d] = Q[b][d] + ALPHA * sum_n Aff[b][n] * ckh[n][d]
// Tiles: 64x128x32, 8 warps, warp tile 32x32.
// A = Aff (k-contiguous). B = ckh viewed as [k=16384][n=512] (n-contiguous),
// loaded via ldmatrix.trans. B smem rows padded to 272B (conflict-free).
// ---------------------------------------------------------------------------
#define G2_ASZ (64 * 80)    // 5120
#define G2_BSZ (32 * 272)   // 8704
#define G2_STG (G2_ASZ + G2_BSZ)

__device__ __forceinline__ void g2_load(u32 smb, int s, int m0, int n0,
                                        int kt, int tid) {
    u32 Ab = smb + s * G2_STG;
    u32 Bb = Ab + G2_ASZ;
    {   // A: 64 rows x 4 chunks = 256 chunks
        int row = tid >> 2;
        int c = tid & 3;
        const char* ga = (const char*)g_aff + ((size_t)(m0 + row) * NK + kt * 32 + c * 8) * 2;
        cp16(Ab + row * 80 + c * 16, ga);
    }
#pragma unroll
    for (int p = 0; p < 2; p++) {  // B: 32 rows x 16 chunks = 512 chunks
        int chunk = tid + p * 256;
        int row = chunk >> 4;
        int c = chunk & 15;
        const char* gb = (const char*)g_ckh + ((size_t)(kt * 32 + row) * D_DIM + n0 + c * 8) * 2;
        cp16(Bb + row * 272 + c * 16, gb);
    }
    cp_commit();
}

__global__ void __launch_bounds__(256) gemm2_kernel(const float* __restrict__ Qorig,
                                                    float* __restrict__ Out) {
    __shared__ __align__(16) char sm[2 * G2_STG];  // 27648 bytes
    const int tid = threadIdx.x;
    const int warp = tid >> 5;
    const int lane = tid & 31;
    const int m0 = blockIdx.y * 64;
    const int n0 = blockIdx.x * 128;
    const int wm = (warp >> 2) * 32;
    const int wn = (warp & 3) * 32;
    const u32 smb = (u32)__cvta_generic_to_shared(sm);

    float acc[2][4][4] = {};

    g2_load(smb, 0, m0, n0, 0, tid);

    const int NT = NK / 32;  // 512
    for (int kt = 0; kt < NT; kt++) {
        if (kt + 1 < NT) {
            g2_load(smb, (kt + 1) & 1, m0, n0, kt + 1, tid);
            cp_wait1();
        } else {
            cp_wait0();
        }
        __syncthreads();

        u32 Ab = smb + (kt & 1) * G2_STG;
        u32 Bb = Ab + G2_ASZ;
#pragma unroll
        for (int ks = 0; ks < 2; ks++) {
            u32 a[2][4];
            u32 b[2][4];
#pragma unroll
            for (int mi = 0; mi < 2; mi++) {
                ldsm_x4(a[mi], Ab + (wm + mi * 16 + (lane & 15)) * 80 + ks * 32 + (lane >> 4) * 16);
            }
#pragma unroll
            for (int j = 0; j < 2; j++) {
                int k = ks * 16 + (lane & 15);
                int n = wn + j * 16 + (lane >> 4) * 8;
                ldsm_x4_t(b[j], Bb + k * 272 + n * 2);
            }
#pragma unroll
            for (int mi = 0; mi < 2; mi++) {
#pragma unroll
                for (int j = 0; j < 2; j++) {
                    mma16816(acc[mi][j * 2 + 0], a[mi], b[j][0], b[j][1]);  // n 0-7
                    mma16816(acc[mi][j * 2 + 1], a[mi], b[j][2], b[j][3]);  // n 8-15
                }
            }
        }
        __syncthreads();
    }

    // Epilogue: out = q + ALPHA * acc
#pragma unroll
    for (int mi = 0; mi < 2; mi++) {
#pragma unroll
        for (int ni = 0; ni < 4; ni++) {
            int col = n0 + wn + ni * 8 + (lane & 3) * 2;
#pragma unroll
            for (int h = 0; h < 2; h++) {
                int row = m0 + wm + mi * 16 + (lane >> 2) + h * 8;
                float2 q = *(const float2*)(Qorig + (size_t)row * D_DIM + col);
                float2 o;
                o.x = fmaf(ALPHA, acc[mi][ni][2 * h + 0], q.x);
                o.y = fmaf(ALPHA, acc[mi][ni][2 * h + 1], q.y);
                *(float2*)(Out + (size_t)row * D_DIM + col) = o;
            }
        }
    }
}

// ---------------------------------------------------------------------------
extern "C" void kernel_launch(void* const* d_in, const int* in_sizes, int n_in,
                              void* d_out, int out_size) {
    const float* qf;
    const float* sk;
    if (in_sizes[0] == NB * D_DIM) {
        qf = (const float*)d_in[0];
        sk = (const float*)d_in[1];
    } else {
        qf = (const float*)d_in[1];
        sk = (const float*)d_in[0];
    }

    norm_rows<<<NK / 8, 256>>>(sk, NK, 1);
    norm_rows<<<NB / 8, 256>>>(qf, NB, 0);

    dim3 g1(NK / 128, NB / 128);   // (128, 32)
    gemm1_kernel<<<g1, 256>>>();

    dim3 g2(D_DIM / 128, NB / 64); // (4, 64)
    gemm2_kernel<<<g2, 256>>>(qf, (float*)d_out);
}

// round 5
// speedup vs baseline: 8.2872x; 1.0666x over previous
#include <cuda_runtime.h>
#include <cuda_bf16.h>
#include <stdint.h>
#include <cstdint>
#include <math.h>

typedef unsigned int u32;

#define D_DIM 512
#define NB 4096
#define NK 16384
#define BETA 5.5f
#define ALPHA 0.5f
#define NSPLIT 2

// bf16 scratch
__device__ __nv_bfloat16 g_qh[(size_t)NB * D_DIM];    // normalized queries (4 MB)
__device__ __nv_bfloat16 g_ckh[(size_t)NK * D_DIM];   // normalized keys    (16 MB)
__device__ __nv_bfloat16 g_aff[(size_t)NB * NK];      // affinity           (128 MB)
__device__ float g_part[(size_t)NSPLIT * NB * D_DIM]; // split-K partials   (16 MB)

// ---------------------------------------------------------------------------
// PTX helpers
// ---------------------------------------------------------------------------
__device__ __forceinline__ void cp16(u32 saddr, const void* g) {
    asm volatile("cp.async.cg.shared.global [%0], [%1], 16;\n" :: "r"(saddr), "l"(g));
}
__device__ __forceinline__ void cp_commit() { asm volatile("cp.async.commit_group;\n"); }
__device__ __forceinline__ void cp_wait_1() { asm volatile("cp.async.wait_group 1;\n"); }
__device__ __forceinline__ void cp_wait_0() { asm volatile("cp.async.wait_group 0;\n"); }

__device__ __forceinline__ void ldsm_x4(u32* r, u32 addr) {
    asm volatile("ldmatrix.sync.aligned.m8n8.x4.shared.b16 {%0,%1,%2,%3}, [%4];\n"
        : "=r"(r[0]), "=r"(r[1]), "=r"(r[2]), "=r"(r[3]) : "r"(addr));
}
__device__ __forceinline__ void ldsm_x4_t(u32* r, u32 addr) {
    asm volatile("ldmatrix.sync.aligned.m8n8.x4.trans.shared.b16 {%0,%1,%2,%3}, [%4];\n"
        : "=r"(r[0]), "=r"(r[1]), "=r"(r[2]), "=r"(r[3]) : "r"(addr));
}
__device__ __forceinline__ void mma16816(float* c, const u32* a, u32 b0, u32 b1) {
    asm volatile(
        "mma.sync.aligned.m16n8k16.row.col.f32.bf16.bf16.f32 "
        "{%0,%1,%2,%3}, {%4,%5,%6,%7}, {%8,%9}, {%0,%1,%2,%3};\n"
        : "+f"(c[0]), "+f"(c[1]), "+f"(c[2]), "+f"(c[3])
        : "r"(a[0]), "r"(a[1]), "r"(a[2]), "r"(a[3]), "r"(b0), "r"(b1));
}

// ---------------------------------------------------------------------------
// Row L2-normalization -> bf16. One warp per 512-float row.
// ---------------------------------------------------------------------------
__global__ void __launch_bounds__(256) norm_rows(const float* __restrict__ src,
                                                 int rows, int dst_sel) {
    int w = (blockIdx.x * blockDim.x + threadIdx.x) >> 5;
    if (w >= rows) return;
    int lane = threadIdx.x & 31;
    __nv_bfloat16* dst = dst_sel ? g_ckh : g_qh;

    const float4* s = (const float4*)(src + (size_t)w * D_DIM);
    float4 v[4];
    float ss = 0.f;
#pragma unroll
    for (int i = 0; i < 4; i++) {
        v[i] = s[lane + 32 * i];
        ss += v[i].x * v[i].x + v[i].y * v[i].y + v[i].z * v[i].z + v[i].w * v[i].w;
    }
#pragma unroll
    for (int o = 16; o; o >>= 1) {
        ss += __shfl_xor_sync(0xffffffffu, ss, o);
    }
    float inv = 1.0f / fmaxf(sqrtf(ss), 1e-12f);

    uint2* d = (uint2*)(dst + (size_t)w * D_DIM);
#pragma unroll
    for (int i = 0; i < 4; i++) {
        __nv_bfloat162 lo = __floats2bfloat162_rn(v[i].x * inv, v[i].y * inv);
        __nv_bfloat162 hi = __floats2bfloat162_rn(v[i].z * inv, v[i].w * inv);
        uint2 u;
        u.x = *(u32*)&lo;
        u.y = *(u32*)&hi;
        d[lane + 32 * i] = u;
    }
}

// ---------------------------------------------------------------------------
// GEMM1: Aff[b][n] = bf16( exp(BETA * dot(qh[b], ckh[n]) - BETA) )
// 128x128x32 tiles, 8 warps (64x32 warp tile), 3-stage cp.async pipeline.
// ---------------------------------------------------------------------------
#define G1_ASZ (128 * 80)           // 10240 bytes A (or B) per stage
#define G1_STG (2 * G1_ASZ)

__device__ __forceinline__ void g1_load(u32 smb, int s, int m0, int n0,
                                        int kt, int tid) {
    u32 Ab = smb + s * G1_STG;
    u32 Bb = Ab + G1_ASZ;
#pragma unroll
    for (int p = 0; p < 2; p++) {
        int chunk = tid + p * 256;          // 0..511
        int row = chunk >> 2;
        int c = chunk & 3;
        const char* ga = (const char*)g_qh + ((size_t)(m0 + row) * D_DIM + kt * 32 + c * 8) * 2;
        cp16(Ab + row * 80 + c * 16, ga);
        const char* gb = (const char*)g_ckh + ((size_t)(n0 + row) * D_DIM + kt * 32 + c * 8) * 2;
        cp16(Bb + row * 80 + c * 16, gb);
    }
    cp_commit();
}

__global__ void __launch_bounds__(256) gemm1_kernel() {
    __shared__ __align__(16) char sm[3 * G1_STG];  // 60 KB
    const int tid = threadIdx.x;
    const int warp = tid >> 5;
    const int lane = tid & 31;
    const int m0 = blockIdx.y * 128;
    const int n0 = blockIdx.x * 128;
    const int wm = (warp >> 2) * 64;
    const int wn = (warp & 3) * 32;
    const u32 smb = (u32)__cvta_generic_to_shared(sm);

    float acc[4][4][4] = {};

    g1_load(smb, 0, m0, n0, 0, tid);
    g1_load(smb, 1, m0, n0, 1, tid);

    const int NT = D_DIM / 32;  // 16
    for (int kt = 0; kt < NT; kt++) {
        cp_wait_1();
        __syncthreads();
        if (kt + 2 < NT) {
            int s = kt + 2;
            g1_load(smb, s - (s / 3) * 3, m0, n0, s, tid);
        }

        int cs = kt - (kt / 3) * 3;
        u32 Ab = smb + cs * G1_STG;
        u32 Bb = Ab + G1_ASZ;
#pragma unroll
        for (int ks = 0; ks < 2; ks++) {
            u32 a[4][4];
            u32 b[2][4];
#pragma unroll
            for (int mi = 0; mi < 4; mi++) {
                ldsm_x4(a[mi], Ab + (wm + mi * 16 + (lane & 15)) * 80 + ks * 32 + (lane >> 4) * 16);
            }
#pragma unroll
            for (int j = 0; j < 2; j++) {
                ldsm_x4(b[j], Bb + (wn + j * 16 + (lane & 15)) * 80 + ks * 32 + (lane >> 4) * 16);
            }
#pragma unroll
            for (int mi = 0; mi < 4; mi++) {
#pragma unroll
                for (int j = 0; j < 2; j++) {
                    mma16816(acc[mi][j * 2 + 0], a[mi], b[j][0], b[j][2]);
                    mma16816(acc[mi][j * 2 + 1], a[mi], b[j][1], b[j][3]);
                }
            }
        }
        __syncthreads();
    }

    // Epilogue: exp + bf16 store
#pragma unroll
    for (int mi = 0; mi < 4; mi++) {
#pragma unroll
        for (int ni = 0; ni < 4; ni++) {
            int col = n0 + wn + ni * 8 + (lane & 3) * 2;
#pragma unroll
            for (int h = 0; h < 2; h++) {
                int row = m0 + wm + mi * 16 + (lane >> 2) + h * 8;
                float e0 = __expf(fmaf(BETA, acc[mi][ni][2 * h + 0], -BETA));
                float e1 = __expf(fmaf(BETA, acc[mi][ni][2 * h + 1], -BETA));
                __nv_bfloat162 v = __floats2bfloat162_rn(e0, e1);
                *(u32*)(&g_aff[(size_t)row * NK + col]) = *(u32*)&v;
            }
        }
    }
}

// ---------------------------------------------------------------------------
// GEMM2 (split-K): Part[z][b][d] = sum_{n in split z} Aff[b][n] * ckh[n][d]
// 64x128 tiles, 8 warps (32x32 warp tile), 3-stage pipeline, grid.z = NSPLIT.
// ---------------------------------------------------------------------------
#define G2_ASZ (64 * 80)    // 5120
#define G2_BSZ (32 * 272)   // 8704
#define G2_STG (G2_ASZ + G2_BSZ)

__device__ __forceinline__ void g2_load(u32 smb, int s, int m0, int n0,
                                        int kt, int tid) {
    u32 Ab = smb + s * G2_STG;
    u32 Bb = Ab + G2_ASZ;
    {   // A: 64 rows x 4 chunks = 256 chunks
        int row = tid >> 2;
        int c = tid & 3;
        const char* ga = (const char*)g_aff + ((size_t)(m0 + row) * NK + kt * 32 + c * 8) * 2;
        cp16(Ab + row * 80 + c * 16, ga);
    }
#pragma unroll
    for (int p = 0; p < 2; p++) {  // B: 32 rows x 16 chunks = 512 chunks
        int chunk = tid + p * 256;
        int row = chunk >> 4;
        int c = chunk & 15;
        const char* gb = (const char*)g_ckh + ((size_t)(kt * 32 + row) * D_DIM + n0 + c * 8) * 2;
        cp16(Bb + row * 272 + c * 16, gb);
    }
    cp_commit();
}

__global__ void __launch_bounds__(256) gemm2_kernel() {
    __shared__ __align__(16) char sm[3 * G2_STG];  // 41472 bytes
    const int tid = threadIdx.x;
    const int warp = tid >> 5;
    const int lane = tid & 31;
    const int m0 = blockIdx.y * 64;
    const int n0 = blockIdx.x * 128;
    const int split = blockIdx.z;
    const int kt0 = split * (NK / NSPLIT / 32);   // starting k-tile
    const u32 smb = (u32)__cvta_generic_to_shared(sm);
    const int wm = (warp >> 2) * 32;
    const int wn = (warp & 3) * 32;

    float acc[2][4][4] = {};

    g2_load(smb, 0, m0, n0, kt0 + 0, tid);
    g2_load(smb, 1, m0, n0, kt0 + 1, tid);

    const int NT = NK / NSPLIT / 32;  // 256
    for (int kt = 0; kt < NT; kt++) {
        cp_wait_1();
        __syncthreads();
        if (kt + 2 < NT) {
            int s = kt + 2;
            g2_load(smb, s - (s / 3) * 3, m0, n0, kt0 + s, tid);
        }

        int cs = kt - (kt / 3) * 3;
        u32 Ab = smb + cs * G2_STG;
        u32 Bb = Ab + G2_ASZ;
#pragma unroll
        for (int ks = 0; ks < 2; ks++) {
            u32 a[2][4];
            u32 b[2][4];
#pragma unroll
            for (int mi = 0; mi < 2; mi++) {
                ldsm_x4(a[mi], Ab + (wm + mi * 16 + (lane & 15)) * 80 + ks * 32 + (lane >> 4) * 16);
            }
#pragma unroll
            for (int j = 0; j < 2; j++) {
                int k = ks * 16 + (lane & 15);
                int n = wn + j * 16 + (lane >> 4) * 8;
                ldsm_x4_t(b[j], Bb + k * 272 + n * 2);
            }
#pragma unroll
            for (int mi = 0; mi < 2; mi++) {
#pragma unroll
                for (int j = 0; j < 2; j++) {
                    mma16816(acc[mi][j * 2 + 0], a[mi], b[j][0], b[j][1]);
                    mma16816(acc[mi][j * 2 + 1], a[mi], b[j][2], b[j][3]);
                }
            }
        }
        __syncthreads();
    }

    // Epilogue: store fp32 partial
    float* part = g_part + (size_t)split * NB * D_DIM;
#pragma unroll
    for (int mi = 0; mi < 2; mi++) {
#pragma unroll
        for (int ni = 0; ni < 4; ni++) {
            int col = n0 + wn + ni * 8 + (lane & 3) * 2;
#pragma unroll
            for (int h = 0; h < 2; h++) {
                int row = m0 + wm + mi * 16 + (lane >> 2) + h * 8;
                float2 o;
                o.x = acc[mi][ni][2 * h + 0];
                o.y = acc[mi][ni][2 * h + 1];
                *(float2*)(part + (size_t)row * D_DIM + col) = o;
            }
        }
    }
}

// ---------------------------------------------------------------------------
// Reduce: out = q + ALPHA * (p0 + p1)
// ---------------------------------------------------------------------------
__global__ void __launch_bounds__(256) reduce_kernel(const float* __restrict__ Qorig,
                                                     float* __restrict__ Out) {
    size_t i = ((size_t)blockIdx.x * blockDim.x + threadIdx.x) * 4;
    float4 q = *(const float4*)(Qorig + i);
    float4 p0 = *(const float4*)(g_part + i);
    float4 p1 = *(const float4*)(g_part + (size_t)NB * D_DIM + i);
    float4 o;
    o.x = fmaf(ALPHA, p0.x + p1.x, q.x);
    o.y = fmaf(ALPHA, p0.y + p1.y, q.y);
    o.z = fmaf(ALPHA, p0.z + p1.z, q.z);
    o.w = fmaf(ALPHA, p0.w + p1.w, q.w);
    *(float4*)(Out + i) = o;
}

// ---------------------------------------------------------------------------
extern "C" void kernel_launch(void* const* d_in, const int* in_sizes, int n_in,
                              void* d_out, int out_size) {
    const float* qf;
    const float* sk;
    if (in_sizes[0] == NB * D_DIM) {
        qf = (const float*)d_in[0];
        sk = (const float*)d_in[1];
    } else {
        qf = (const float*)d_in[1];
        sk = (const float*)d_in[0];
    }

    norm_rows<<<NK / 8, 256>>>(sk, NK, 1);
    norm_rows<<<NB / 8, 256>>>(qf, NB, 0);

    dim3 g1(NK / 128, NB / 128);          // (128, 32)
    gemm1_kernel<<<g1, 256>>>();

    dim3 g2(D_DIM / 128, NB / 64, NSPLIT); // (4, 64, 2)
    gemm2_kernel<<<g2, 256>>>();

    reduce_kernel<<<(NB * D_DIM) / (256 * 4), 256>>>(qf, (float*)d_out);
}